// round 3
// baseline (speedup 1.0000x reference)
#include <cuda_runtime.h>
#include <cstdint>

#define BB 4
#define CC 256
#define HH 56
#define WW 56
#define CO 128
#define NT 49
#define HW 3136

typedef unsigned long long u64;

// ---- device-global scratch (no allocations allowed) ----
__device__ __align__(16) u64   g_W1d[2 * CC * NT * 64];       // dup-packed weights, 12.8MB
__device__ __align__(16) float g_part[4 * BB * CO * HW];      // split-K partials, 25.7MB
__device__ __align__(16) float g_attn[BB * NT * HW];          // softmax attention

// ---------- packed fp32x2 helpers (SASS FFMA2) ----------
__device__ __forceinline__ u64 pack2(float x, float y) {
    u64 r;
    asm("mov.b64 %0, {%1, %2};" : "=l"(r)
        : "r"(__float_as_uint(x)), "r"(__float_as_uint(y)));
    return r;
}
__device__ __forceinline__ void fma2(u64& d, u64 a, u64 b) {
    asm("fma.rn.f32x2 %0, %1, %2, %0;" : "+l"(d) : "l"(a), "l"(b));
}
__device__ __forceinline__ float2 unpack2(u64 v) {
    float2 f;
    asm("mov.b64 {%0, %1}, %2;" : "=f"(f.x), "=f"(f.y) : "l"(v));
    return f;
}
__device__ __forceinline__ u64 lds64(const float* p) {
    return *reinterpret_cast<const u64*>(p);
}

// =====================================================================
// Kernel 0: duplicate-pack W1 into g_W1d[cb][ci][tap][co]  (u64 = (w,w))
// =====================================================================
__global__ void __launch_bounds__(256) prep_w1(const float* __restrict__ W1)
{
    int idx = blockIdx.x * 256 + threadIdx.x;   // 2*256*49*64 = 1,605,632
    int co  = idx & 63;
    int t   = idx >> 6;
    int tap = t % NT;
    int r   = t / NT;          // cb*256 + ci
    int ci  = r & 255;
    int cb  = r >> 8;
    float w = W1[((cb * 64 + co) * CC + ci) * NT + tap];
    g_W1d[idx] = pack2(w, w);
}

// =====================================================================
// Kernel A: conv1 (7x7 dil-2 pad-6) split-K partials -> g_part
// Grid (28, 4, 8): h-pair, b, (co-half * 4 ci-quarters). 224 threads.
// Thread: 1 h-row (hl) x 4 co x 8 px. 16 packed f32x2 accumulators.
// =====================================================================
__global__ void __launch_bounds__(224) conv1_kernel(const float* __restrict__ x)
{
    __shared__ __align__(16) u64   ws[NT * 64];     // [tap][co] dup-packed, 25088B
    __shared__ __align__(16) float xs[2][7][68];    // 2 rows x 7 dil-rows x cols[-6..61]

    const int b   = blockIdx.y;
    const int cb  = blockIdx.z >> 2;     // co half
    const int q   = blockIdx.z & 3;      // ci quarter
    const int ci0 = q * 64;
    const int tid = threadIdx.x;
    const int hl  = tid / 112;           // 0/1 within h-pair (warp-uniform)
    const int r   = tid - hl * 112;
    const int cg  = r & 15;              // 16 co-quads
    const int pg  = r >> 4;              // 7 pixel groups
    const int p0  = pg * 8;              // 8 px per thread
    const int h   = blockIdx.x * 2 + hl;

    u64 acc[16];
#pragma unroll
    for (int t = 0; t < 16; ++t) acc[t] = 0ull;   // bits 0 == (+0.f,+0.f)

    for (int ci = ci0; ci < ci0 + 64; ++ci) {
        __syncthreads();
        // ---- weights: straight coalesced copy (already packed + laid out) ----
        {
            const ulonglong2* src = reinterpret_cast<const ulonglong2*>(
                g_W1d + (size_t)(cb * CC + ci) * (NT * 64));
            ulonglong2* dst = reinterpret_cast<ulonglong2*>(ws);
#pragma unroll
            for (int t = 0; t < 7; ++t)           // 7*224 = 1568 x 16B
                dst[tid + t * 224] = src[tid + t * 224];
        }
        // ---- x tile: 2 rows x 7 dilated rows x 68 cols, zero-padded ----
        {
            const float* xp = x + ((size_t)b * CC + ci) * HW;
            const int h0 = blockIdx.x * 2;
#pragma unroll
            for (int t = 0; t < 5; ++t) {
                int e = tid + t * 224;
                if (e < 952) {
                    int hh  = e / 476; int rr = e - hh * 476;
                    int i   = rr / 68; int col = rr - i * 68;
                    int row = h0 + hh - 6 + 2 * i;
                    int gcol = col - 6;
                    float v = 0.f;
                    if ((unsigned)row < HH && (unsigned)gcol < WW)
                        v = xp[row * WW + gcol];
                    xs[hh][i][col] = v;
                }
            }
        }
        __syncthreads();

#pragma unroll
        for (int i = 0; i < 7; ++i) {
            const u64* xrow = reinterpret_cast<const u64*>(&xs[hl][i][p0]);
            const u64* wrow = &ws[i * 7 * 64 + 4 * cg];
            u64 xw0 = xrow[0], xw1 = xrow[1], xw2 = xrow[2], xw3 = xrow[3];
#pragma unroll
            for (int j = 0; j < 7; ++j) {
                ulonglong2 wa = *reinterpret_cast<const ulonglong2*>(wrow + j * 64);
                ulonglong2 wb = *reinterpret_cast<const ulonglong2*>(wrow + j * 64 + 2);
                fma2(acc[0],  wa.x, xw0); fma2(acc[1],  wa.x, xw1);
                fma2(acc[2],  wa.x, xw2); fma2(acc[3],  wa.x, xw3);
                fma2(acc[4],  wa.y, xw0); fma2(acc[5],  wa.y, xw1);
                fma2(acc[6],  wa.y, xw2); fma2(acc[7],  wa.y, xw3);
                fma2(acc[8],  wb.x, xw0); fma2(acc[9],  wb.x, xw1);
                fma2(acc[10], wb.x, xw2); fma2(acc[11], wb.x, xw3);
                fma2(acc[12], wb.y, xw0); fma2(acc[13], wb.y, xw1);
                fma2(acc[14], wb.y, xw2); fma2(acc[15], wb.y, xw3);
                xw0 = xw1; xw1 = xw2; xw2 = xw3;
                if (j < 6) xw3 = xrow[j + 4];
            }
        }
    }

    // ---- store partials (no bias here; added in kernel B) ----
#pragma unroll
    for (int c = 0; c < 4; ++c) {
        int co = cb * 64 + 4 * cg + c;
        float* dst = g_part + ((size_t)(q * BB + b) * CO + co) * HW + h * WW + p0;
#pragma unroll
        for (int m = 0; m < 4; ++m)
            reinterpret_cast<u64*>(dst)[m] = acc[c * 4 + m];
    }
}

// =====================================================================
// Kernel B: sum 4 split-K slices + b1, conv2 (1x1, 128->49) + b2,
//           softmax over 49 -> g_attn.  Grid (56,4), 256 threads.
// =====================================================================
__global__ void __launch_bounds__(256) conv2_softmax_kernel(
    const float* __restrict__ W2, const float* __restrict__ b1,
    const float* __restrict__ b2)
{
    __shared__ float k1s[128][57];
    __shared__ float ls[49][57];
    const int h = blockIdx.x;
    const int b = blockIdx.y;
    const int tid = threadIdx.x;

    for (int t = tid; t < 128 * 56; t += 256) {
        int c = t / 56, p = t - c * 56;
        size_t base = (size_t)(b * CO + c) * HW + h * WW + p;
        float v = b1[c];
#pragma unroll
        for (int q = 0; q < 4; ++q)
            v += g_part[(size_t)q * BB * CO * HW + base];
        k1s[c][p] = v;
    }
    __syncthreads();

    for (int idx = tid; idx < 49 * 56; idx += 256) {
        int kk = idx / 56, p = idx - kk * 56;
        float acc = b2[kk];
        const float* wr = &W2[kk * 128];
#pragma unroll 8
        for (int c = 0; c < 128; ++c)
            acc += __ldg(&wr[c]) * k1s[c][p];
        ls[kk][p] = acc;
    }
    __syncthreads();

    if (tid < 56) {
        int p = tid;
        float m = -1e30f;
#pragma unroll
        for (int kk = 0; kk < 49; ++kk) m = fmaxf(m, ls[kk][p]);
        float s = 0.f;
#pragma unroll
        for (int kk = 0; kk < 49; ++kk) {
            float e = expf(ls[kk][p] - m);
            ls[kk][p] = e;
            s += e;
        }
        float inv = 1.f / s;
#pragma unroll
        for (int kk = 0; kk < 49; ++kk) ls[kk][p] *= inv;
    }
    __syncthreads();

    for (int t = tid; t < 49 * 56; t += 256) {
        int kk = t / 56, p = t - kk * 56;
        g_attn[((size_t)b * NT + kk) * HW + h * WW + p] = ls[kk][p];
    }
}

// =====================================================================
// Kernel C: weighted local sum over 49 dilated taps -> out
// Grid (56, 4, 2), 224 threads.
// =====================================================================
__global__ void __launch_bounds__(224) gather_kernel(
    const float* __restrict__ x, float* __restrict__ out)
{
    __shared__ __align__(16) float at[49][58];
    __shared__ __align__(16) float xs[16][7][68];
    const int h = blockIdx.x;
    const int b = blockIdx.y;
    const int chalf = blockIdx.z * 128;
    const int tid = threadIdx.x;

    for (int t = tid; t < 49 * 56; t += 224) {
        int kk = t / 56, p = t - kk * 56;
        at[kk][p] = g_attn[((size_t)b * NT + kk) * HW + h * WW + p];
    }

    const int pg = tid % 14;
    const int cl = tid / 14;
    const int p0 = pg * 4;

    for (int ch = 0; ch < 8; ++ch) {
        __syncthreads();
        for (int t = tid; t < 16 * 476; t += 224) {
            int c = t / 476, rr = t - c * 476;
            int i = rr / 68, col = rr - i * 68;
            int row = h - 6 + 2 * i;
            int gcol = col - 6;
            float v = 0.f;
            if ((unsigned)row < HH && (unsigned)gcol < WW)
                v = x[((size_t)(b * CC + chalf + ch * 16 + c)) * HW + row * WW + gcol];
            xs[c][i][col] = v;
        }
        __syncthreads();

        u64 a0 = 0ull, a1 = 0ull;
#pragma unroll
        for (int i = 0; i < 7; ++i) {
            const float* xrow = &xs[cl][i][p0];
            u64 xv0 = lds64(xrow);
            u64 xv1 = lds64(xrow + 2);
#pragma unroll
            for (int j = 0; j < 7; ++j) {
                u64 av0 = lds64(&at[i * 7 + j][p0]);
                u64 av1 = lds64(&at[i * 7 + j][p0 + 2]);
                fma2(a0, av0, xv0);
                fma2(a1, av1, xv1);
                xv0 = xv1;
                xv1 = lds64(xrow + 2 * j + 4);
            }
        }
        int c = chalf + ch * 16 + cl;
        size_t o = (size_t)(b * CC + c) * HW + h * WW + p0;
        float2 r0 = unpack2(a0), r1 = unpack2(a1);
        *reinterpret_cast<float2*>(&out[o]) = r0;
        *reinterpret_cast<float2*>(&out[o + 2]) = r1;
    }
}

// =====================================================================
extern "C" void kernel_launch(void* const* d_in, const int* in_sizes, int n_in,
                              void* d_out, int out_size)
{
    const float* x  = (const float*)d_in[0];
    const float* W1 = (const float*)d_in[1];
    const float* b1 = (const float*)d_in[2];
    const float* W2 = (const float*)d_in[3];
    const float* b2 = (const float*)d_in[4];
    for (int i = 0; i < n_in; ++i) {
        switch (in_sizes[i]) {
            case BB * CC * HW: x  = (const float*)d_in[i]; break;
            case CO * CC * NT: W1 = (const float*)d_in[i]; break;
            case CO:           b1 = (const float*)d_in[i]; break;
            case NT * CO:      W2 = (const float*)d_in[i]; break;
            case NT:           b2 = (const float*)d_in[i]; break;
            default: break;
        }
    }
    float* out = (float*)d_out;

    prep_w1<<<6272, 256>>>(W1);
    conv1_kernel<<<dim3(28, 4, 8), 224>>>(x);
    conv2_softmax_kernel<<<dim3(56, 4), 256>>>(W2, b1, b2);
    gather_kernel<<<dim3(56, 4, 2), 224>>>(x, out);
}

// round 5
// speedup vs baseline: 2.6783x; 2.6783x over previous
#include <cuda_runtime.h>
#include <cstdint>

#define BB 4
#define CC 256
#define HH 56
#define WW 56
#define CO 128
#define NT 49
#define HW 3136
#define GTOT 392          // 49 taps x 8 ci-blocks of 32

typedef unsigned long long u64;

// ---- device-global scratch ----
__device__ __align__(16) float g_W1b[GTOT * 4096];   // tf32 weights [g][co][k], 6.4MB
__device__ __align__(16) float g_k1[BB * CO * HW];   // conv1 output
__device__ __align__(16) float g_attn[BB * NT * HW]; // softmax attention

// ---------- helpers ----------
__device__ __forceinline__ uint32_t smem_to_u32(const void* p) {
    uint32_t a;
    asm("{ .reg .u64 t; cvta.to.shared.u64 t, %1; cvt.u32.u64 %0, t; }" : "=r"(a) : "l"(p));
    return a;
}
__device__ __forceinline__ uint32_t cvt_tf32(float f) {
    uint32_t u;
    asm("cvt.rn.tf32.f32 %0, %1;" : "=r"(u) : "f"(f));
    return u;
}
#define CP16(dst, src) \
    asm volatile("cp.async.cg.shared.global [%0], [%1], 16;" :: "r"(dst), "l"(src) : "memory")
#define CP_COMMIT() asm volatile("cp.async.commit_group;" ::: "memory")
#define CP_WAIT0()  asm volatile("cp.async.wait_group 0;" ::: "memory")

#define MMA_TF32(d, a, bfr) \
    asm volatile("mma.sync.aligned.m16n8k8.row.col.f32.tf32.tf32.f32 " \
        "{%0,%1,%2,%3}, {%4,%5,%6,%7}, {%8,%9}, {%0,%1,%2,%3};" \
        : "+f"((d)[0]), "+f"((d)[1]), "+f"((d)[2]), "+f"((d)[3]) \
        : "r"((a)[0]), "r"((a)[1]), "r"((a)[2]), "r"((a)[3]), \
          "r"((bfr)[0]), "r"((bfr)[1]))

__device__ __forceinline__ void sts128(uint32_t a, uint32_t r0, uint32_t r1,
                                       uint32_t r2, uint32_t r3) {
    asm volatile("st.shared.v4.b32 [%0], {%1,%2,%3,%4};"
                 :: "r"(a), "r"(r0), "r"(r1), "r"(r2), "r"(r3) : "memory");
}
// ---------- f32x2 helpers for scalar kernels ----------
__device__ __forceinline__ void fma2(u64& d, u64 a, u64 b) {
    asm("fma.rn.f32x2 %0, %1, %2, %0;" : "+l"(d) : "l"(a), "l"(b));
}
__device__ __forceinline__ float2 unpack2(u64 v) {
    float2 f;
    asm("mov.b64 {%0, %1}, %2;" : "=f"(f.x), "=f"(f.y) : "l"(v));
    return f;
}
__device__ __forceinline__ u64 lds64(const float* p) {
    return *reinterpret_cast<const u64*>(p);
}

// =====================================================================
// Kernel 0: bake W1 -> g_W1b[g][co][k] as tf32 (cvt.rn).  g = tap*8+cib.
// =====================================================================
__global__ void __launch_bounds__(256) prep_w1(const float* __restrict__ W1)
{
    int idx = blockIdx.x * 256 + threadIdx.x;     // 392*4096 = 1,605,632
    int g = idx >> 12, e = idx & 4095;
    int co = e >> 5, k = e & 31;
    int tap = g >> 3, cib = g & 7;
    float wv = W1[((size_t)co * CC + cib * 32 + k) * NT + tap];
    g_W1b[idx] = __uint_as_float(cvt_tf32(wv));
}

// =====================================================================
// Kernel A: conv1 as tf32 mma.sync GEMM. Grid 98, 128 threads (4 warps).
// CTA tile 128px x 128co; warp tile 64x64; K loop: 392 groups of 32.
// Double-buffered smem; A-LDGs for g+1 issued before mma of g.
// =====================================================================
#define ASTRIDE 36
#define ABYTES  (128 * ASTRIDE * 4)     // 18432
#define CONV1_SMEM (4 * ABYTES)         // As0,As1,Bs0,Bs1 = 73728

__global__ void __launch_bounds__(128, 1) conv1_mma(const float* __restrict__ x)
{
    extern __shared__ __align__(16) char smem[];
    float* const As0 = (float*)smem;
    float* const Bs0 = (float*)(smem + 2 * ABYTES);

    const int tid = threadIdx.x;
    const int wid = tid >> 5, lane = tid & 31;
    const int g8 = lane >> 2, t4 = lane & 3;
    const int m0 = (wid >> 1) * 64, n0 = (wid & 1) * 64;

    // this thread's pixel row (A row r = tid)
    const int px = blockIdx.x * 128 + tid;
    const int b = px / HW, rem = px % HW;
    const int h = rem / WW, w0 = rem % WW;

    const uint32_t sb = smem_to_u32(smem);
    const uint32_t a_st_base = sb + (uint32_t)tid * (ASTRIDE * 4);
    const uint32_t b_cp_base = sb + 2 * (uint32_t)ABYTES;

    float acc[4][8][4];
#pragma unroll
    for (int i = 0; i < 4; ++i)
#pragma unroll
        for (int j = 0; j < 8; ++j)
#pragma unroll
            for (int c = 0; c < 4; ++c) acc[i][j][c] = 0.f;

    float v[32];

    // ---- A patch LDGs for group g into regs ----
    auto lda = [&](int g) {
        int tap = g >> 3, cib = g & 7;
        int di = tap / 7, dj = tap - di * 7;
        int ir = h - 6 + 2 * di, ic = w0 - 6 + 2 * dj;
        bool ok = ((unsigned)ir < HH) && ((unsigned)ic < WW);
        const float* xb = x + ((size_t)(b * CC + cib * 32)) * HW + ir * WW + ic;
#pragma unroll
        for (int k = 0; k < 32; ++k)
            v[k] = ok ? __ldg(xb + (size_t)k * HW) : 0.f;
    };
    // ---- B tile cp.async for group g into buffer buf ----
    auto ldb = [&](int g, int buf) {
        const char* src = (const char*)(g_W1b + (size_t)g * 4096);
        uint32_t dstb = b_cp_base + (uint32_t)buf * ABYTES;
#pragma unroll
        for (int i = 0; i < 8; ++i) {
            int c = tid + i * 128;            // float4 chunk id 0..1023
            int co = c >> 3, kq = c & 7;
            uint32_t d = dstb + (uint32_t)(co * ASTRIDE + kq * 4) * 4;
            CP16(d, src + (size_t)c * 16);
        }
    };
    // ---- store A regs (cvt to tf32) into buffer buf ----
    auto sta = [&](int buf) {
        uint32_t dst = a_st_base + (uint32_t)buf * ABYTES;
#pragma unroll
        for (int k = 0; k < 32; k += 4)
            sts128(dst + k * 4, cvt_tf32(v[k]), cvt_tf32(v[k + 1]),
                   cvt_tf32(v[k + 2]), cvt_tf32(v[k + 3]));
    };

    // prologue: group 0
    lda(0); ldb(0, 0); CP_COMMIT();
    sta(0);
    CP_WAIT0();
    __syncthreads();

    for (int g = 0; g < GTOT; ++g) {
        const int cur = g & 1;
        if (g + 1 < GTOT) { lda(g + 1); ldb(g + 1, cur ^ 1); CP_COMMIT(); }

        const float* ap = As0 + (size_t)cur * (ABYTES / 4) + m0 * ASTRIDE;
        const float* bp = Bs0 + (size_t)cur * (ABYTES / 4) + n0 * ASTRIDE;
#pragma unroll
        for (int kk = 0; kk < 4; ++kk) {
            const int k0 = kk * 8;
            uint32_t af[4][4], bf[8][2];
#pragma unroll
            for (int i = 0; i < 4; ++i) {
                const float* ar = ap + (16 * i + g8) * ASTRIDE + k0 + t4;
                af[i][0] = __float_as_uint(ar[0]);
                af[i][1] = __float_as_uint(ar[8 * ASTRIDE]);
                af[i][2] = __float_as_uint(ar[4]);
                af[i][3] = __float_as_uint(ar[8 * ASTRIDE + 4]);
            }
#pragma unroll
            for (int j = 0; j < 8; ++j) {
                const float* br = bp + (8 * j + g8) * ASTRIDE + k0 + t4;
                bf[j][0] = __float_as_uint(br[0]);
                bf[j][1] = __float_as_uint(br[4]);
            }
#pragma unroll
            for (int i = 0; i < 4; ++i)
#pragma unroll
                for (int j = 0; j < 8; ++j)
                    MMA_TF32(acc[i][j], af[i], bf[j]);
        }

        if (g + 1 < GTOT) { sta(cur ^ 1); CP_WAIT0(); }
        __syncthreads();
    }

    // ---- epilogue: transpose via smem (reuse buffers), coalesced STG ----
    float* const Cs = (float*)smem;          // [co][px] stride 132
#pragma unroll
    for (int i = 0; i < 4; ++i)
#pragma unroll
        for (int j = 0; j < 8; ++j) {
            int row0 = m0 + 16 * i + g8;
            int col0 = n0 + 8 * j + 2 * t4;
            Cs[(col0)     * 132 + row0]     = acc[i][j][0];
            Cs[(col0 + 1) * 132 + row0]     = acc[i][j][1];
            Cs[(col0)     * 132 + row0 + 8] = acc[i][j][2];
            Cs[(col0 + 1) * 132 + row0 + 8] = acc[i][j][3];
        }
    __syncthreads();

#pragma unroll 4
    for (int co = 0; co < CO; ++co)
        g_k1[(size_t)(b * CO + co) * HW + rem] = Cs[co * 132 + tid];
}

// =====================================================================
// Kernel B: +b1, conv2 (1x1, 128->49) + b2, softmax(49) -> g_attn
// =====================================================================
__global__ void __launch_bounds__(256) conv2_softmax_kernel(
    const float* __restrict__ W2, const float* __restrict__ b1,
    const float* __restrict__ b2)
{
    __shared__ float k1s[128][57];
    __shared__ float ls[49][57];
    const int h = blockIdx.x, b = blockIdx.y, tid = threadIdx.x;

    for (int t = tid; t < 128 * 56; t += 256) {
        int c = t / 56, p = t - c * 56;
        k1s[c][p] = g_k1[(size_t)(b * CO + c) * HW + h * WW + p] + b1[c];
    }
    __syncthreads();

    for (int idx = tid; idx < 49 * 56; idx += 256) {
        int kk = idx / 56, p = idx - kk * 56;
        float acc = b2[kk];
        const float* wr = &W2[kk * 128];
#pragma unroll 8
        for (int c = 0; c < 128; ++c) acc += __ldg(&wr[c]) * k1s[c][p];
        ls[kk][p] = acc;
    }
    __syncthreads();

    if (tid < 56) {
        int p = tid;
        float m = -1e30f;
#pragma unroll
        for (int kk = 0; kk < 49; ++kk) m = fmaxf(m, ls[kk][p]);
        float s = 0.f;
#pragma unroll
        for (int kk = 0; kk < 49; ++kk) {
            float e = expf(ls[kk][p] - m);
            ls[kk][p] = e;
            s += e;
        }
        float inv = 1.f / s;
#pragma unroll
        for (int kk = 0; kk < 49; ++kk) ls[kk][p] *= inv;
    }
    __syncthreads();

    for (int t = tid; t < 49 * 56; t += 256) {
        int kk = t / 56, p = t - kk * 56;
        g_attn[((size_t)b * NT + kk) * HW + h * WW + p] = ls[kk][p];
    }
}

// =====================================================================
// Kernel C: weighted local sum over 49 dilated taps -> out
// =====================================================================
__global__ void __launch_bounds__(224) gather_kernel(
    const float* __restrict__ x, float* __restrict__ out)
{
    __shared__ __align__(16) float at[49][58];
    __shared__ __align__(16) float xs[16][7][68];
    const int h = blockIdx.x, b = blockIdx.y;
    const int chalf = blockIdx.z * 128;
    const int tid = threadIdx.x;

    for (int t = tid; t < 49 * 56; t += 224) {
        int kk = t / 56, p = t - kk * 56;
        at[kk][p] = g_attn[((size_t)b * NT + kk) * HW + h * WW + p];
    }

    const int pg = tid % 14, cl = tid / 14, p0 = pg * 4;

    for (int ch = 0; ch < 8; ++ch) {
        __syncthreads();
        for (int t = tid; t < 16 * 476; t += 224) {
            int c = t / 476, rr = t - c * 476;
            int i = rr / 68, col = rr - i * 68;
            int row = h - 6 + 2 * i, gcol = col - 6;
            float v = 0.f;
            if ((unsigned)row < HH && (unsigned)gcol < WW)
                v = x[((size_t)(b * CC + chalf + ch * 16 + c)) * HW + row * WW + gcol];
            xs[c][i][col] = v;
        }
        __syncthreads();

        u64 a0 = 0ull, a1 = 0ull;
#pragma unroll
        for (int i = 0; i < 7; ++i) {
            const float* xrow = &xs[cl][i][p0];
            u64 xv0 = lds64(xrow), xv1 = lds64(xrow + 2);
#pragma unroll
            for (int j = 0; j < 7; ++j) {
                fma2(a0, lds64(&at[i * 7 + j][p0]), xv0);
                fma2(a1, lds64(&at[i * 7 + j][p0 + 2]), xv1);
                xv0 = xv1;
                xv1 = lds64(xrow + 2 * j + 4);
            }
        }
        size_t o = (size_t)(b * CC + chalf + ch * 16 + cl) * HW + h * WW + p0;
        float2 r0 = unpack2(a0), r1 = unpack2(a1);
        *reinterpret_cast<float2*>(&out[o]) = r0;
        *reinterpret_cast<float2*>(&out[o + 2]) = r1;
    }
}

// =====================================================================
extern "C" void kernel_launch(void* const* d_in, const int* in_sizes, int n_in,
                              void* d_out, int out_size)
{
    const float* x  = (const float*)d_in[0];
    const float* W1 = (const float*)d_in[1];
    const float* b1 = (const float*)d_in[2];
    const float* W2 = (const float*)d_in[3];
    const float* b2 = (const float*)d_in[4];
    for (int i = 0; i < n_in; ++i) {
        switch (in_sizes[i]) {
            case BB * CC * HW: x  = (const float*)d_in[i]; break;
            case CO * CC * NT: W1 = (const float*)d_in[i]; break;
            case CO:           b1 = (const float*)d_in[i]; break;
            case NT * CO:      W2 = (const float*)d_in[i]; break;
            case NT:           b2 = (const float*)d_in[i]; break;
            default: break;
        }
    }
    float* out = (float*)d_out;

    cudaFuncSetAttribute(conv1_mma, cudaFuncAttributeMaxDynamicSharedMemorySize,
                         CONV1_SMEM);
    prep_w1<<<6272, 256>>>(W1);
    conv1_mma<<<98, 128, CONV1_SMEM>>>(x);
    conv2_softmax_kernel<<<dim3(56, 4), 256>>>(W2, b1, b2);
    gather_kernel<<<dim3(56, 4, 2), 224>>>(x, out);
}